// round 1
// baseline (speedup 1.0000x reference)
#include <cuda_runtime.h>
#include <cuda_fp16.h>
#include <mma.h>

using namespace nvcuda;

#define BB   8
#define NN   2048
#define FIN  128
#define FO   64
#define NP   96                 // padded hw cols: 64 feat + 1 denom + 31 zero
#define ROWS_TOTAL (BB*NN)      // 16384

// ---------------- scratch (device globals; no allocation allowed) -----------
__device__ __align__(16) float  g_h [ROWS_TOTAL * FO];   // 4 MB
__device__             float  g_s2[ROWS_TOTAL];
__device__             float  g_mx[BB];
__device__ __align__(16) __half g_hw[ROWS_TOTAL * NP];   // 3 MB

// ============================================================================
// Kernel 1: h = x @ W  (fp32), plus s2 = h @ a2.
// 64 rows/block, 256 threads as 16x16, each thread 4x4 micro-tile.
// ============================================================================
__global__ void __launch_bounds__(256) h_kernel(const float* __restrict__ x,
                                                const float* __restrict__ W,
                                                const float* __restrict__ a2)
{
    __shared__ float sW[FIN][FO];   // 32 KB, whole W
    __shared__ float sX[64][36];    // 64 rows x 32-k chunk (+pad)

    const int t    = threadIdx.x;
    const int row0 = blockIdx.x * 64;

    // load W (2048 float4)
    #pragma unroll
    for (int q = 0; q < 8; q++) {
        int idx = q * 256 + t;
        ((float4*)sW)[idx] = ((const float4*)W)[idx];
    }

    const int ty = t >> 4;     // 0..15 -> row group (4 rows)
    const int tx = t & 15;     // 0..15 -> col group (4 cols)

    float acc[4][4];
    #pragma unroll
    for (int i = 0; i < 4; i++)
        #pragma unroll
        for (int j = 0; j < 4; j++) acc[i][j] = 0.f;

    for (int k0 = 0; k0 < FIN; k0 += 32) {
        __syncthreads();   // protect sX from previous iter readers (also covers sW 1st time)
        #pragma unroll
        for (int q = 0; q < 8; q++) {
            int idx = q * 256 + t;
            int r = idx >> 5, c = idx & 31;
            sX[r][c] = x[(size_t)(row0 + r) * FIN + k0 + c];
        }
        __syncthreads();

        #pragma unroll
        for (int c = 0; c < 32; c++) {
            float4 wv = *(const float4*)&sW[k0 + c][tx * 4];
            float xv[4];
            #pragma unroll
            for (int i = 0; i < 4; i++) xv[i] = sX[ty * 4 + i][c];
            #pragma unroll
            for (int i = 0; i < 4; i++) {
                acc[i][0] = fmaf(xv[i], wv.x, acc[i][0]);
                acc[i][1] = fmaf(xv[i], wv.y, acc[i][1]);
                acc[i][2] = fmaf(xv[i], wv.z, acc[i][2]);
                acc[i][3] = fmaf(xv[i], wv.w, acc[i][3]);
            }
        }
    }

    // s2 partials over this thread's 4 cols
    float a2v[4];
    #pragma unroll
    for (int j = 0; j < 4; j++) a2v[j] = __ldg(&a2[tx * 4 + j]);

    float s2p[4];
    #pragma unroll
    for (int i = 0; i < 4; i++) {
        float p = 0.f;
        #pragma unroll
        for (int j = 0; j < 4; j++) p = fmaf(acc[i][j], a2v[j], p);
        s2p[i] = p;
    }
    // reduce across the 16 tx lanes (xor masks stay within 16-lane halves)
    #pragma unroll
    for (int s = 1; s < 16; s <<= 1)
        #pragma unroll
        for (int i = 0; i < 4; i++)
            s2p[i] += __shfl_xor_sync(0xffffffffu, s2p[i], s);

    if (tx == 0)
        #pragma unroll
        for (int i = 0; i < 4; i++) g_s2[row0 + ty * 4 + i] = s2p[i];

    #pragma unroll
    for (int i = 0; i < 4; i++) {
        float4 v = make_float4(acc[i][0], acc[i][1], acc[i][2], acc[i][3]);
        *(float4*)&g_h[(size_t)(row0 + ty * 4 + i) * FO + tx * 4] = v;
    }
}

// ============================================================================
// Kernel 2: per-batch max of s2 (numerics only)
// ============================================================================
__global__ void __launch_bounds__(256) max_kernel()
{
    const int b = blockIdx.x, t = threadIdx.x;
    float m = -1e30f;
    for (int i = t; i < NN; i += 256) m = fmaxf(m, g_s2[b * NN + i]);
    __shared__ float sm[256];
    sm[t] = m;
    __syncthreads();
    for (int s = 128; s > 0; s >>= 1) {
        if (t < s) sm[t] = fmaxf(sm[t], sm[t + s]);
        __syncthreads();
    }
    if (t == 0) g_mx[b] = sm[0];
}

// ============================================================================
// Kernel 3: hw[row][f] = fp16( g*h )  f<64 ;  g at f==64 ; 0 for 65..95
// ============================================================================
__global__ void hw_kernel()
{
    const int row = blockIdx.x;
    const int f   = threadIdx.x;     // 0..95
    const int b   = row >> 11;
    const float gj = expf(g_s2[row] - g_mx[b]);
    float v = 0.f;
    if (f < FO)       v = gj * g_h[(size_t)row * FO + f];
    else if (f == FO) v = gj;
    g_hw[(size_t)row * NP + f] = __float2half(v);
}

// ============================================================================
// Kernel 4 (main): C = M @ hw, rowwise divide by col 64, + bias.
//   - 256 blocks = 8 batches x 32 row-tiles of 64
//   - 256 threads = 8 warps: 4 (M) x 2 (N); warp tile 16 x 48 (3 n-frags)
//   - adj tile loaded fp32 -> converted to exact 0/1 fp16 (diag forced 1)
//   - single-stage register prefetch overlaps LDG of tile k+1 with MMA of k
// ============================================================================
__global__ void __launch_bounds__(256) gat_main(const float* __restrict__ adj,
                                                const float* __restrict__ bias,
                                                float* __restrict__ out)
{
    constexpr int LA = 72;    // sA stride (halves)
    constexpr int LB = 104;   // sB stride (halves)
    constexpr int LC = 96;    // sC stride (floats)

    __shared__ __align__(16) unsigned char smem_raw[64 * LC * 4];  // 24576 B
    __half* sA = (__half*)smem_raw;                 // [64][72]
    __half* sB = (__half*)(smem_raw + 64 * LA * 2); // [64][104]
    float*  sC = (float*)smem_raw;                  // [64][96] (epilogue reuse)

    const int t   = threadIdx.x;
    const int blk = blockIdx.x;
    const int b   = blk >> 5;           // 32 m-tiles per batch
    const int m0  = (blk & 31) * 64;

    const float*  adjB = adj + (size_t)b * NN * NN;
    const __half* hwB  = g_hw + (size_t)b * NN * NP;

    const int w  = t >> 5;
    const int wm = w >> 1;              // 0..3
    const int wn = w & 1;               // 0..1

    wmma::fragment<wmma::accumulator, 16, 16, 16, float> acc[3];
    #pragma unroll
    for (int i = 0; i < 3; i++) wmma::fill_fragment(acc[i], 0.f);

    float4 pa[4];
    uint4  pb[3];

    // ---- prefetch k0 = 0 ----
    #pragma unroll
    for (int q = 0; q < 4; q++) {
        int idx = q * 256 + t; int r = idx >> 4, c4 = idx & 15;
        pa[q] = __ldg((const float4*)&adjB[(size_t)(m0 + r) * NN + c4 * 4]);
    }
    #pragma unroll
    for (int q = 0; q < 3; q++) {
        int idx = q * 256 + t; int r = idx / 12, c = idx % 12;
        pb[q] = *(const uint4*)&hwB[(size_t)r * NP + c * 8];
    }

    for (int k0 = 0; k0 < NN; k0 += 64) {
        // ---- store prefetched tile to smem (convert adj -> exact 0/1 fp16) ----
        #pragma unroll
        for (int q = 0; q < 4; q++) {
            int idx = q * 256 + t; int r = idx >> 4, c4 = idx & 15;
            int ig = m0 + r, jg = k0 + c4 * 4;
            float4 v = pa[q];
            __half2 h01 = __floats2half2_rn(
                (v.x > 0.5f || ig == jg    ) ? 1.f : 0.f,
                (v.y > 0.5f || ig == jg + 1) ? 1.f : 0.f);
            __half2 h23 = __floats2half2_rn(
                (v.z > 0.5f || ig == jg + 2) ? 1.f : 0.f,
                (v.w > 0.5f || ig == jg + 3) ? 1.f : 0.f);
            __half2* dst = (__half2*)&sA[r * LA + c4 * 4];
            dst[0] = h01; dst[1] = h23;
        }
        #pragma unroll
        for (int q = 0; q < 3; q++) {
            int idx = q * 256 + t; int r = idx / 12, c = idx % 12;
            *(uint4*)&sB[r * LB + c * 8] = pb[q];
        }

        // ---- prefetch next tile (LDGs in flight across sync + MMA) ----
        if (k0 + 64 < NN) {
            #pragma unroll
            for (int q = 0; q < 4; q++) {
                int idx = q * 256 + t; int r = idx >> 4, c4 = idx & 15;
                pa[q] = __ldg((const float4*)&adjB[(size_t)(m0 + r) * NN + (k0 + 64) + c4 * 4]);
            }
            #pragma unroll
            for (int q = 0; q < 3; q++) {
                int idx = q * 256 + t; int r = idx / 12, c = idx % 12;
                pb[q] = *(const uint4*)&hwB[(size_t)(k0 + 64 + r) * NP + c * 8];
            }
        }
        __syncthreads();

        // ---- MMA: 64-deep K chunk ----
        #pragma unroll
        for (int kk = 0; kk < 64; kk += 16) {
            wmma::fragment<wmma::matrix_a, 16, 16, 16, __half, wmma::row_major> af;
            wmma::load_matrix_sync(af, &sA[(wm * 16) * LA + kk], LA);
            #pragma unroll
            for (int nf = 0; nf < 3; nf++) {
                wmma::fragment<wmma::matrix_b, 16, 16, 16, __half, wmma::row_major> bf;
                wmma::load_matrix_sync(bf, &sB[kk * LB + wn * 48 + nf * 16], LB);
                wmma::mma_sync(acc[nf], af, bf, acc[nf]);
            }
        }
        __syncthreads();   // protect smem before next store
    }

    // ---- epilogue: divide by denominator column (64), add bias ----
    #pragma unroll
    for (int nf = 0; nf < 3; nf++)
        wmma::store_matrix_sync(&sC[(wm * 16) * LC + wn * 48 + nf * 16],
                                acc[nf], LC, wmma::mem_row_major);
    __syncthreads();

    #pragma unroll
    for (int q = 0; q < 16; q++) {
        int idx = q * 256 + t;
        int r = idx >> 6, f = idx & 63;
        float den = sC[r * LC + FO];
        float val = sC[r * LC + f] / den + __ldg(&bias[f]);
        out[((size_t)b * NN + m0 + r) * FO + f] = val;
    }
}

// ============================================================================
// launch
// ============================================================================
extern "C" void kernel_launch(void* const* d_in, const int* in_sizes, int n_in,
                              void* d_out, int out_size)
{
    const float* x    = (const float*)d_in[0];   // [8,2048,128]
    const float* adj  = (const float*)d_in[1];   // [8,2048,2048]
    const float* W    = (const float*)d_in[2];   // [128,64]
    const float* a    = (const float*)d_in[3];   // [128,1]
    const float* bias = (const float*)d_in[4];   // [64]
    float* out = (float*)d_out;

    const float* a2 = a + FO;   // s1 term cancels in softmax; only a2 needed

    h_kernel<<<ROWS_TOTAL / 64, 256>>>(x, W, a2);
    max_kernel<<<BB, 256>>>();
    hw_kernel<<<ROWS_TOTAL, NP>>>();
    gat_main<<<BB * (NN / 64), 256>>>(adj, bias, out);
}